// round 16
// baseline (speedup 1.0000x reference)
#include <cuda_runtime.h>
#include <cstdint>

#define NN 50000
#define EE 800000
#define SCAN_BLOCKS 49

// Scratch (device globals; no dynamic allocation allowed)
__device__ float g_h1[(size_t)NN * 128];   // W1 @ nfeat + b_ne per node (tf32 MMA)
__device__ float g_WcT[32 * 128];          // (W2 @ W_edge)T, tf32-rounded: [c][j]
__device__ uint2 g_WcF[2048];              // prepacked edge-B frags
__device__ uint2 g_WnF[16384];             // prepacked node-B frags: [W1 | W_self], 256 cols
__device__ int   g_deg[NN];
__device__ int   g_incl[NN];
__device__ int   g_cursor[NN];
__device__ int   g_bsum[64];
__device__ int   g_bpre[64];
__device__ int4  g_epk[EE];                // (edge id, src, dst, 0) grouped by dst
__device__ int   g_neigh[(size_t)NN * 128]; // float bits, segment-max accumulator

// ---------------- helpers ----------------
__device__ __forceinline__ unsigned tf32r(float x) {
    unsigned r; asm("cvt.rna.tf32.f32 %0, %1;" : "=r"(r) : "f"(x)); return r;
}
__device__ __forceinline__ void mma_tf32(float& c0, float& c1, float& c2, float& c3,
                                         unsigned a0, unsigned a1, unsigned a2, unsigned a3,
                                         unsigned b0, unsigned b1) {
    asm("mma.sync.aligned.m16n8k8.row.col.f32.tf32.tf32.f32 "
        "{%0,%1,%2,%3}, {%4,%5,%6,%7}, {%8,%9}, {%0,%1,%2,%3};"
        : "+f"(c0), "+f"(c1), "+f"(c2), "+f"(c3)
        : "r"(a0), "r"(a1), "r"(a2), "r"(a3), "r"(b0), "r"(b1));
}

// ---------------- prep: Wc = W2 @ W_edge, transposed, tf32-rounded ----------------
__global__ void k_wc(const float* __restrict__ W_ne, const float* __restrict__ W_edge) {
    int c = blockIdx.x;    // 0..31
    int o = threadIdx.x;   // 0..127
    float s = 0.f;
    #pragma unroll 8
    for (int j = 0; j < 128; j++)
        s += W_ne[o * 256 + 128 + j] * W_edge[j * 32 + c];
    g_WcT[c * 128 + o] = __uint_as_float(tf32r(s));
}

// ---------------- prep: pack edge-B fragments ----------------
__global__ void k_wpack() {
    int slot = blockIdx.x * 256 + threadIdx.x;   // 2048 slots
    int lane = slot & 31, ks = (slot >> 5) & 3, nt = slot >> 7;
    int tid4 = lane & 3, g = lane >> 2;
    int k0 = ks * 8 + tid4, j = nt * 8 + g;
    g_WcF[slot] = make_uint2(__float_as_uint(g_WcT[k0 * 128 + j]),
                             __float_as_uint(g_WcT[(k0 + 4) * 128 + j]));
}

// ---------------- prep: pack node-B frags ([W1 | W_self] tf32) ----------------
__global__ void k_prep(const float* __restrict__ W_ne, const float* __restrict__ W_self) {
    int slot = blockIdx.x * 256 + threadIdx.x;   // 16384 slots
    int lane = slot & 31, ks = (slot >> 5) & 15, nt = slot >> 9;  // nt 0..31
    int tid4 = lane & 3, g = lane >> 2;
    int k0 = ks * 8 + tid4, j = nt * 8 + g;
    float b0, b1;
    if (j < 128) {
        b0 = W_ne[j * 256 + k0];
        b1 = W_ne[j * 256 + k0 + 4];
    } else {
        b0 = W_self[(j - 128) * 128 + k0];
        b1 = W_self[(j - 128) * 128 + k0 + 4];
    }
    g_WnF[slot] = make_uint2(tf32r(b0), tf32r(b1));
}

// ---------------- zero neigh (own stream; only k_edge needs it) ----------------
__global__ void k_zero_neigh() {
    int idx = blockIdx.x * blockDim.x + threadIdx.x;  // 6250*256 = NN*128/4
    int4 z = {0, 0, 0, 0};
    ((int4*)g_neigh)[idx] = z;
}

// ---------------- zero deg (tiny; heads the build chain) ----------------
__global__ void k_zero_deg() {
    int n = blockIdx.x * blockDim.x + threadIdx.x;
    if (n < NN) g_deg[n] = 0;
}

// ---------------- degree count ----------------
__global__ void k_count(const int* __restrict__ dst) {
    int e = blockIdx.x * blockDim.x + threadIdx.x;
    if (e < EE) atomicAdd(&g_deg[dst[e]], 1);
}

// ---------------- scan A ----------------
__global__ void k_scanA() {
    int n = blockIdx.x * 1024 + threadIdx.x;
    int lane = threadIdx.x & 31, w = threadIdx.x >> 5;
    int v = (n < NN) ? g_deg[n] : 0;
    int x = v;
    #pragma unroll
    for (int d = 1; d < 32; d <<= 1) {
        int y = __shfl_up_sync(0xffffffffu, x, d);
        if (lane >= d) x += y;
    }
    __shared__ int ws[32];
    if (lane == 31) ws[w] = x;
    __syncthreads();
    if (w == 0) {
        int y = ws[lane];
        #pragma unroll
        for (int d = 1; d < 32; d <<= 1) {
            int z = __shfl_up_sync(0xffffffffu, y, d);
            if (lane >= d) y += z;
        }
        ws[lane] = y;
    }
    __syncthreads();
    int incl = x + ((w > 0) ? ws[w - 1] : 0);
    if (n < NN) g_incl[n] = incl;
    if (threadIdx.x == 1023) g_bsum[blockIdx.x] = incl;
}

// ---------------- scan B ----------------
__global__ void k_scanB() {
    __shared__ int s[64];
    int t = threadIdx.x;
    int v = (t < SCAN_BLOCKS) ? g_bsum[t] : 0;
    s[t] = v;
    __syncthreads();
    for (int d = 1; d < 64; d <<= 1) {
        int y = (t >= d) ? s[t - d] : 0;
        __syncthreads();
        s[t] += y;
        __syncthreads();
    }
    if (t < SCAN_BLOCKS) g_bpre[t] = s[t] - v;
}

// ---------------- scan C: cursors ----------------
__global__ void k_scanC() {
    int n = blockIdx.x * 1024 + threadIdx.x;
    if (n < NN)
        g_cursor[n] = g_incl[n] - g_deg[n] + g_bpre[blockIdx.x];
}

// ---------------- scatter: one packed int4 store per edge ----------------
__global__ void k_scatter(const int* __restrict__ dst, const int* __restrict__ src) {
    int e = blockIdx.x * blockDim.x + threadIdx.x;
    if (e < EE) {
        int d = dst[e];
        int s = src[e];
        int p = atomicAdd(&g_cursor[d], 1);
        g_epk[p] = make_int4(e, s, d, 0);
    }
}

// ---------------- node GEMM: tf32 mma, 32 nodes/block, fused [h1 | self] ----------------
__global__ void __launch_bounds__(128) k_node(const float* __restrict__ nfeat,
                       const float* __restrict__ b_ne,
                       const float* __restrict__ b_self,
                       float* __restrict__ out) {
    __shared__ unsigned sA[32 * 132];   // 32 nodes x 128 k, tf32 bits
    __shared__ float sB[256];           // [b_ne | b_self]

    int t = threadIdx.x;
    int base = blockIdx.x * 32;

    {
        int r = t >> 2, cb = (t & 3) * 32;
        int node = base + r; if (node >= NN) node = NN - 1;   // clamp (tail)
        const float4* p = (const float4*)(nfeat + (size_t)node * 128 + cb);
        unsigned* dr = sA + r * 132 + cb;
        #pragma unroll
        for (int i = 0; i < 8; i++) {
            float4 v = p[i];
            dr[i * 4 + 0] = tf32r(v.x); dr[i * 4 + 1] = tf32r(v.y);
            dr[i * 4 + 2] = tf32r(v.z); dr[i * 4 + 3] = tf32r(v.w);
        }
    }
    if (t < 128) { sB[t] = b_ne[t]; sB[128 + t] = b_self[t]; }
    __syncthreads();

    int lane = t & 31, w = t >> 5;
    int tid4 = lane & 3, g = lane >> 2;
    int m0 = (w >> 1) * 16;       // rows 0 or 16
    int ntb = (w & 1) * 16;       // 0 => h1 cols, 16 => self cols

    float acc[16][4];
    #pragma unroll
    for (int nt = 0; nt < 16; nt++)
        #pragma unroll
        for (int i = 0; i < 4; i++) acc[nt][i] = 0.f;

    #pragma unroll
    for (int ks = 0; ks < 16; ks++) {
        int k0 = ks * 8;
        unsigned a0 = sA[(m0 + g) * 132 + k0 + tid4];
        unsigned a1 = sA[(m0 + g + 8) * 132 + k0 + tid4];
        unsigned a2 = sA[(m0 + g) * 132 + k0 + tid4 + 4];
        unsigned a3 = sA[(m0 + g + 8) * 132 + k0 + tid4 + 4];
        #pragma unroll
        for (int nt = 0; nt < 16; nt++) {
            uint2 bb = g_WnF[((ntb + nt) * 16 + ks) * 32 + lane];
            mma_tf32(acc[nt][0], acc[nt][1], acc[nt][2], acc[nt][3], a0, a1, a2, a3, bb.x, bb.y);
        }
    }

    int na = base + m0 + g, nb = na + 8;
    bool va = (na < NN), vb = (nb < NN);
    float* dsta = (ntb == 0) ? g_h1 : out;
    int jo = (ntb == 0) ? 0 : 128;
    #pragma unroll
    for (int nt = 0; nt < 16; nt++) {
        int jc = (ntb + nt) * 8 + 2 * tid4;
        float bx = sB[jc], by = sB[jc + 1];
        if (va) *(float2*)&dsta[(size_t)na * 128 + (jc - jo)] =
            make_float2(acc[nt][0] + bx, acc[nt][1] + by);
        if (vb) *(float2*)&dsta[(size_t)nb * 128 + (jc - jo)] =
            make_float2(acc[nt][2] + bx, acc[nt][3] + by);
    }
}

// ---------------- edge kernel: tf32 mma; interior runs use plain stores ----------------
__global__ void __launch_bounds__(128) k_edge(const float* __restrict__ etype) {
    __shared__ unsigned sEt[64 * 36];
    __shared__ float sM[64 * 132];
    __shared__ int sSrc[64];
    __shared__ int sDst[64];

    int t = threadIdx.x;
    int base = blockIdx.x * 64;   // 12500 blocks

    if (t < 64) {
        int4 pk = g_epk[base + t];
        sSrc[t] = pk.y;
        sDst[t] = pk.z;
    }
    {
        int r = t >> 1, cb = (t & 1) * 16;
        int e = g_epk[base + r].x;
        const float4* p = (const float4*)(etype + (size_t)e * 32 + cb);
        float4 v0 = p[0], v1 = p[1], v2 = p[2], v3 = p[3];
        uint4* dv = (uint4*)(sEt + r * 36 + cb);   // 16B aligned: 36r+cb ≡ 0 mod 4
        dv[0] = make_uint4(tf32r(v0.x), tf32r(v0.y), tf32r(v0.z), tf32r(v0.w));
        dv[1] = make_uint4(tf32r(v1.x), tf32r(v1.y), tf32r(v1.z), tf32r(v1.w));
        dv[2] = make_uint4(tf32r(v2.x), tf32r(v2.y), tf32r(v2.z), tf32r(v2.w));
        dv[3] = make_uint4(tf32r(v3.x), tf32r(v3.y), tf32r(v3.z), tf32r(v3.w));
    }
    __syncthreads();

    // ---- MMA phase: warp owns 2 m-tiles x 8 nt-tiles; each B-frag feeds 2 MMAs ----
    {
        int lane = t & 31, w = t >> 5;
        int tid4 = lane & 3, g = lane >> 2;
        int mb = (w & 1) * 32;        // row base: 0 or 32 (2 m-tiles of 16)
        int ntb = (w >> 1) * 8;       // nt tile base: 0 or 8

        unsigned a[2][4][4];
        #pragma unroll
        for (int mt = 0; mt < 2; mt++) {
            int m0 = mb + mt * 16;
            #pragma unroll
            for (int ks = 0; ks < 4; ks++) {
                int k0 = ks * 8;
                a[mt][ks][0] = sEt[(m0 + g) * 36 + k0 + tid4];
                a[mt][ks][1] = sEt[(m0 + g + 8) * 36 + k0 + tid4];
                a[mt][ks][2] = sEt[(m0 + g) * 36 + k0 + tid4 + 4];
                a[mt][ks][3] = sEt[(m0 + g + 8) * 36 + k0 + tid4 + 4];
            }
        }
        const float* row0 = g_h1 + (size_t)sSrc[mb + g] * 128;
        const float* row1 = g_h1 + (size_t)sSrc[mb + g + 8] * 128;
        const float* row2 = g_h1 + (size_t)sSrc[mb + 16 + g] * 128;
        const float* row3 = g_h1 + (size_t)sSrc[mb + 16 + g + 8] * 128;

        #pragma unroll
        for (int nt = 0; nt < 8; nt++) {
            int ntg = ntb + nt;
            int jb = ntg * 8 + 2 * tid4;
            uint2 bb0 = g_WcF[(ntg * 4 + 0) * 32 + lane];
            uint2 bb1 = g_WcF[(ntg * 4 + 1) * 32 + lane];
            uint2 bb2 = g_WcF[(ntg * 4 + 2) * 32 + lane];
            uint2 bb3 = g_WcF[(ntg * 4 + 3) * 32 + lane];
            // m-tile 0
            {
                float2 ha = *(const float2*)&row0[jb];
                float2 hb = *(const float2*)&row1[jb];
                float c0 = ha.x, c1 = ha.y, c2 = hb.x, c3 = hb.y;
                mma_tf32(c0, c1, c2, c3, a[0][0][0], a[0][0][1], a[0][0][2], a[0][0][3], bb0.x, bb0.y);
                mma_tf32(c0, c1, c2, c3, a[0][1][0], a[0][1][1], a[0][1][2], a[0][1][3], bb1.x, bb1.y);
                mma_tf32(c0, c1, c2, c3, a[0][2][0], a[0][2][1], a[0][2][2], a[0][2][3], bb2.x, bb2.y);
                mma_tf32(c0, c1, c2, c3, a[0][3][0], a[0][3][1], a[0][3][2], a[0][3][3], bb3.x, bb3.y);
                *(float2*)&sM[(mb + g) * 132 + jb]     = make_float2(c0, c1);
                *(float2*)&sM[(mb + g + 8) * 132 + jb] = make_float2(c2, c3);
            }
            // m-tile 1
            {
                float2 ha = *(const float2*)&row2[jb];
                float2 hb = *(const float2*)&row3[jb];
                float c0 = ha.x, c1 = ha.y, c2 = hb.x, c3 = hb.y;
                mma_tf32(c0, c1, c2, c3, a[1][0][0], a[1][0][1], a[1][0][2], a[1][0][3], bb0.x, bb0.y);
                mma_tf32(c0, c1, c2, c3, a[1][1][0], a[1][1][1], a[1][1][2], a[1][1][3], bb1.x, bb1.y);
                mma_tf32(c0, c1, c2, c3, a[1][2][0], a[1][2][1], a[1][2][2], a[1][2][3], bb2.x, bb2.y);
                mma_tf32(c0, c1, c2, c3, a[1][3][0], a[1][3][1], a[1][3][2], a[1][3][3], bb3.x, bb3.y);
                *(float2*)&sM[(mb + 16 + g) * 132 + jb]     = make_float2(c0, c1);
                *(float2*)&sM[(mb + 16 + g + 8) * 132 + jb] = make_float2(c2, c3);
            }
        }
    }
    __syncthreads();

    // epilogue: thread t owns column j=t; segmented max over 64 CSR-ordered rows.
    // A run that starts at r>0 and ends at a d-change is fully inside this window
    // (dst-sorted), so no other block touches it -> plain store into zeroed neigh.
    // Only the first run and the final run can span windows -> atomicMax.
    {
        int j = t;
        float cur = 0.f;
        int dprev = sDst[0];
        int rstart = 0;
        #pragma unroll 8
        for (int r = 0; r < 64; r++) {
            int d = sDst[r];
            float v = sM[r * 132 + j];
            if (d != dprev) {
                int* slot = &g_neigh[(size_t)dprev * 128 + j];
                if (rstart > 0) *slot = __float_as_int(cur);
                else atomicMax(slot, __float_as_int(cur));
                cur = 0.f;
                dprev = d;
                rstart = r;
            }
            cur = fmaxf(cur, v);
        }
        atomicMax(&g_neigh[(size_t)dprev * 128 + j], __float_as_int(cur));
    }
}

// ---------------- final: out = self + (1+eps)*neigh ----------------
__global__ void k_final(const float* __restrict__ eps, float* __restrict__ out) {
    float s = 1.0f + eps[0];
    int idx = blockIdx.x * blockDim.x + threadIdx.x;  // NN*128/4
    float4 o = ((float4*)out)[idx];
    int4 nb = ((const int4*)g_neigh)[idx];
    o.x = fmaf(s, __int_as_float(nb.x), o.x);
    o.y = fmaf(s, __int_as_float(nb.y), o.y);
    o.z = fmaf(s, __int_as_float(nb.z), o.z);
    o.w = fmaf(s, __int_as_float(nb.w), o.w);
    ((float4*)out)[idx] = o;
}

extern "C" void kernel_launch(void* const* d_in, const int* in_sizes, int n_in,
                              void* d_out, int out_size) {
    const float* nfeat  = (const float*)d_in[0];
    const float* etype  = (const float*)d_in[1];
    const int*   src    = (const int*)d_in[2];
    const int*   dst    = (const int*)d_in[3];
    const float* W_edge = (const float*)d_in[4];
    const float* W_ne   = (const float*)d_in[5];
    const float* b_ne   = (const float*)d_in[6];
    const float* W_self = (const float*)d_in[7];
    const float* b_self = (const float*)d_in[8];
    const float* eps    = (const float*)d_in[9];
    float* out = (float*)d_out;

    // Fork/join with two extra streams; all created AND destroyed per call so
    // the harness memory checkpoints see zero delta (destroy after rejoin).
    cudaStream_t s1, s2;
    cudaStreamCreateWithFlags(&s1, cudaStreamNonBlocking);
    cudaStreamCreateWithFlags(&s2, cudaStreamNonBlocking);
    cudaEvent_t e0, e1, e2;
    cudaEventCreateWithFlags(&e0, cudaEventDisableTiming);
    cudaEventCreateWithFlags(&e1, cudaEventDisableTiming);
    cudaEventCreateWithFlags(&e2, cudaEventDisableTiming);

    cudaEventRecord(e0, 0);          // fork point on the main stream

    // s1: weights + node GEMM chain
    cudaStreamWaitEvent(s1, e0, 0);
    k_wc<<<32, 128, 0, s1>>>(W_ne, W_edge);
    k_wpack<<<8, 256, 0, s1>>>();
    k_prep<<<64, 256, 0, s1>>>(W_ne, W_self);
    k_node<<<(NN + 31) / 32, 128, 0, s1>>>(nfeat, b_ne, b_self, out);
    cudaEventRecord(e1, s1);

    // s2: neigh zero (only needed by k_edge)
    cudaStreamWaitEvent(s2, e0, 0);
    k_zero_neigh<<<6250, 256, 0, s2>>>();
    cudaEventRecord(e2, s2);

    // main stream: CSR build chain
    k_zero_deg<<<(NN + 255) / 256, 256>>>();
    k_count<<<(EE + 255) / 256, 256>>>(dst);
    k_scanA<<<SCAN_BLOCKS, 1024>>>();
    k_scanB<<<1, 64>>>();
    k_scanC<<<SCAN_BLOCKS, 1024>>>();
    k_scatter<<<(EE + 255) / 256, 256>>>(dst, src);

    // join: k_edge needs g_WcF + g_h1 (s1), zeroed neigh (s2), CSR (main)
    cudaStreamWaitEvent(0, e1, 0);
    cudaStreamWaitEvent(0, e2, 0);
    k_edge<<<EE / 64, 128>>>(etype);
    k_final<<<(NN * 128 / 4) / 256, 256>>>(eps, out);

    cudaEventDestroy(e0);
    cudaEventDestroy(e1);
    cudaEventDestroy(e2);
    cudaStreamDestroy(s1);
    cudaStreamDestroy(s2);
}

// round 17
// speedup vs baseline: 1.0433x; 1.0433x over previous
#include <cuda_runtime.h>
#include <cstdint>

#define NN 50000
#define EE 800000
#define SCAN_BLOCKS 49

// Scratch (device globals; no dynamic allocation allowed)
__device__ float g_h1[(size_t)NN * 128];   // W1 @ nfeat + b_ne per node (tf32 MMA)
__device__ float g_WcT[32 * 128];          // (W2 @ W_edge)T, tf32-rounded: [c][j]
__device__ uint2 g_WcF[2048];              // prepacked edge-B frags
__device__ uint2 g_WnF[16384];             // prepacked node-B frags: [W1 | W_self], 256 cols
__device__ int   g_deg[NN];
__device__ int   g_incl[NN];
__device__ int   g_cursor[NN];
__device__ int   g_bsum[64];
__device__ int   g_bpre[64];
__device__ int4  g_epk[EE];                // (edge id, src, dst, 0) grouped by dst
__device__ int   g_neigh[(size_t)NN * 128]; // float bits, atomicMax accumulator

// ---------------- helpers ----------------
__device__ __forceinline__ unsigned tf32r(float x) {
    unsigned r; asm("cvt.rna.tf32.f32 %0, %1;" : "=r"(r) : "f"(x)); return r;
}
__device__ __forceinline__ void mma_tf32(float& c0, float& c1, float& c2, float& c3,
                                         unsigned a0, unsigned a1, unsigned a2, unsigned a3,
                                         unsigned b0, unsigned b1) {
    asm("mma.sync.aligned.m16n8k8.row.col.f32.tf32.tf32.f32 "
        "{%0,%1,%2,%3}, {%4,%5,%6,%7}, {%8,%9}, {%0,%1,%2,%3};"
        : "+f"(c0), "+f"(c1), "+f"(c2), "+f"(c3)
        : "r"(a0), "r"(a1), "r"(a2), "r"(a3), "r"(b0), "r"(b1));
}

// ---------------- prep: Wc = W2 @ W_edge, transposed, tf32-rounded ----------------
__global__ void k_wc(const float* __restrict__ W_ne, const float* __restrict__ W_edge) {
    int c = blockIdx.x;    // 0..31
    int o = threadIdx.x;   // 0..127
    float s = 0.f;
    #pragma unroll 8
    for (int j = 0; j < 128; j++)
        s += W_ne[o * 256 + 128 + j] * W_edge[j * 32 + c];
    g_WcT[c * 128 + o] = __uint_as_float(tf32r(s));
}

// ---------------- prep: pack edge-B fragments ----------------
__global__ void k_wpack() {
    int slot = blockIdx.x * 256 + threadIdx.x;   // 2048 slots
    int lane = slot & 31, ks = (slot >> 5) & 3, nt = slot >> 7;
    int tid4 = lane & 3, g = lane >> 2;
    int k0 = ks * 8 + tid4, j = nt * 8 + g;
    g_WcF[slot] = make_uint2(__float_as_uint(g_WcT[k0 * 128 + j]),
                             __float_as_uint(g_WcT[(k0 + 4) * 128 + j]));
}

// ---------------- prep: pack node-B frags ([W1 | W_self] tf32) ----------------
__global__ void k_prep(const float* __restrict__ W_ne, const float* __restrict__ W_self) {
    int slot = blockIdx.x * 256 + threadIdx.x;   // 16384 slots
    int lane = slot & 31, ks = (slot >> 5) & 15, nt = slot >> 9;  // nt 0..31
    int tid4 = lane & 3, g = lane >> 2;
    int k0 = ks * 8 + tid4, j = nt * 8 + g;
    float b0, b1;
    if (j < 128) {
        b0 = W_ne[j * 256 + k0];
        b1 = W_ne[j * 256 + k0 + 4];
    } else {
        b0 = W_self[(j - 128) * 128 + k0];
        b1 = W_self[(j - 128) * 128 + k0 + 4];
    }
    g_WnF[slot] = make_uint2(tf32r(b0), tf32r(b1));
}

// ---------------- zero neigh (own stream; only k_edge needs it) ----------------
__global__ void k_zero_neigh() {
    int idx = blockIdx.x * blockDim.x + threadIdx.x;  // 6250*256 = NN*128/4
    int4 z = {0, 0, 0, 0};
    ((int4*)g_neigh)[idx] = z;
}

// ---------------- zero deg (tiny; heads the build chain) ----------------
__global__ void k_zero_deg() {
    int n = blockIdx.x * blockDim.x + threadIdx.x;
    if (n < NN) g_deg[n] = 0;
}

// ---------------- degree count ----------------
__global__ void k_count(const int* __restrict__ dst) {
    int e = blockIdx.x * blockDim.x + threadIdx.x;
    if (e < EE) atomicAdd(&g_deg[dst[e]], 1);
}

// ---------------- scan A ----------------
__global__ void k_scanA() {
    int n = blockIdx.x * 1024 + threadIdx.x;
    int lane = threadIdx.x & 31, w = threadIdx.x >> 5;
    int v = (n < NN) ? g_deg[n] : 0;
    int x = v;
    #pragma unroll
    for (int d = 1; d < 32; d <<= 1) {
        int y = __shfl_up_sync(0xffffffffu, x, d);
        if (lane >= d) x += y;
    }
    __shared__ int ws[32];
    if (lane == 31) ws[w] = x;
    __syncthreads();
    if (w == 0) {
        int y = ws[lane];
        #pragma unroll
        for (int d = 1; d < 32; d <<= 1) {
            int z = __shfl_up_sync(0xffffffffu, y, d);
            if (lane >= d) y += z;
        }
        ws[lane] = y;
    }
    __syncthreads();
    int incl = x + ((w > 0) ? ws[w - 1] : 0);
    if (n < NN) g_incl[n] = incl;
    if (threadIdx.x == 1023) g_bsum[blockIdx.x] = incl;
}

// ---------------- scan B ----------------
__global__ void k_scanB() {
    __shared__ int s[64];
    int t = threadIdx.x;
    int v = (t < SCAN_BLOCKS) ? g_bsum[t] : 0;
    s[t] = v;
    __syncthreads();
    for (int d = 1; d < 64; d <<= 1) {
        int y = (t >= d) ? s[t - d] : 0;
        __syncthreads();
        s[t] += y;
        __syncthreads();
    }
    if (t < SCAN_BLOCKS) g_bpre[t] = s[t] - v;
}

// ---------------- scan C: cursors ----------------
__global__ void k_scanC() {
    int n = blockIdx.x * 1024 + threadIdx.x;
    if (n < NN)
        g_cursor[n] = g_incl[n] - g_deg[n] + g_bpre[blockIdx.x];
}

// ---------------- scatter: one packed int4 store per edge ----------------
__global__ void k_scatter(const int* __restrict__ dst, const int* __restrict__ src) {
    int e = blockIdx.x * blockDim.x + threadIdx.x;
    if (e < EE) {
        int d = dst[e];
        int s = src[e];
        int p = atomicAdd(&g_cursor[d], 1);
        g_epk[p] = make_int4(e, s, d, 0);
    }
}

// ---------------- node GEMM: tf32 mma, 32 nodes/block, fused [h1 | self] ----------------
__global__ void __launch_bounds__(128) k_node(const float* __restrict__ nfeat,
                       const float* __restrict__ b_ne,
                       const float* __restrict__ b_self,
                       float* __restrict__ out) {
    __shared__ unsigned sA[32 * 132];   // 32 nodes x 128 k, tf32 bits
    __shared__ float sB[256];           // [b_ne | b_self]

    int t = threadIdx.x;
    int base = blockIdx.x * 32;

    {
        int r = t >> 2, cb = (t & 3) * 32;
        int node = base + r; if (node >= NN) node = NN - 1;   // clamp (tail)
        const float4* p = (const float4*)(nfeat + (size_t)node * 128 + cb);
        unsigned* dr = sA + r * 132 + cb;
        #pragma unroll
        for (int i = 0; i < 8; i++) {
            float4 v = p[i];
            dr[i * 4 + 0] = tf32r(v.x); dr[i * 4 + 1] = tf32r(v.y);
            dr[i * 4 + 2] = tf32r(v.z); dr[i * 4 + 3] = tf32r(v.w);
        }
    }
    if (t < 128) { sB[t] = b_ne[t]; sB[128 + t] = b_self[t]; }
    __syncthreads();

    int lane = t & 31, w = t >> 5;
    int tid4 = lane & 3, g = lane >> 2;
    int m0 = (w >> 1) * 16;       // rows 0 or 16
    int ntb = (w & 1) * 16;       // 0 => h1 cols, 16 => self cols

    float acc[16][4];
    #pragma unroll
    for (int nt = 0; nt < 16; nt++)
        #pragma unroll
        for (int i = 0; i < 4; i++) acc[nt][i] = 0.f;

    #pragma unroll
    for (int ks = 0; ks < 16; ks++) {
        int k0 = ks * 8;
        unsigned a0 = sA[(m0 + g) * 132 + k0 + tid4];
        unsigned a1 = sA[(m0 + g + 8) * 132 + k0 + tid4];
        unsigned a2 = sA[(m0 + g) * 132 + k0 + tid4 + 4];
        unsigned a3 = sA[(m0 + g + 8) * 132 + k0 + tid4 + 4];
        #pragma unroll
        for (int nt = 0; nt < 16; nt++) {
            uint2 bb = g_WnF[((ntb + nt) * 16 + ks) * 32 + lane];
            mma_tf32(acc[nt][0], acc[nt][1], acc[nt][2], acc[nt][3], a0, a1, a2, a3, bb.x, bb.y);
        }
    }

    int na = base + m0 + g, nb = na + 8;
    bool va = (na < NN), vb = (nb < NN);
    float* dsta = (ntb == 0) ? g_h1 : out;
    int jo = (ntb == 0) ? 0 : 128;
    #pragma unroll
    for (int nt = 0; nt < 16; nt++) {
        int jc = (ntb + nt) * 8 + 2 * tid4;
        float bx = sB[jc], by = sB[jc + 1];
        if (va) *(float2*)&dsta[(size_t)na * 128 + (jc - jo)] =
            make_float2(acc[nt][0] + bx, acc[nt][1] + by);
        if (vb) *(float2*)&dsta[(size_t)nb * 128 + (jc - jo)] =
            make_float2(acc[nt][2] + bx, acc[nt][3] + by);
    }
}

// ---------------- edge kernel: tf32 mma, 64 edges/block, 256 threads (8 warps) ----------------
// Same smem footprint as the 128-thread version (5 blocks/SM) but 40 warps/SM:
// per-block phase latency halves; epilogue serial chain 64 -> 32 iterations.
__global__ void __launch_bounds__(256) k_edge(const float* __restrict__ etype) {
    __shared__ unsigned sEt[64 * 36];
    __shared__ float sM[64 * 132];
    __shared__ int sSrc[64];
    __shared__ int sDst[64];

    int t = threadIdx.x;
    int base = blockIdx.x * 64;   // 12500 blocks

    if (t < 64) {
        int4 pk = g_epk[base + t];
        sSrc[t] = pk.y;
        sDst[t] = pk.z;
    }
    // stage etype: 4 threads per row, 8 floats each (2x uint4 STS)
    {
        int r = t >> 2, cb = (t & 3) * 8;
        int e = g_epk[base + r].x;
        const float4* p = (const float4*)(etype + (size_t)e * 32 + cb);
        float4 v0 = p[0], v1 = p[1];
        uint4* dv = (uint4*)(sEt + r * 36 + cb);   // 36r + 8q ≡ 0 mod 4
        dv[0] = make_uint4(tf32r(v0.x), tf32r(v0.y), tf32r(v0.z), tf32r(v0.w));
        dv[1] = make_uint4(tf32r(v1.x), tf32r(v1.y), tf32r(v1.z), tf32r(v1.w));
    }
    __syncthreads();

    // ---- MMA phase: 8 warps; warp owns 1 m-tile x 8 nt-tiles ----
    {
        int lane = t & 31, w = t >> 5;
        int tid4 = lane & 3, g = lane >> 2;
        int m0 = (w & 3) * 16;        // m-tile 0..3
        int ntb = (w >> 2) * 8;       // nt group 0 or 8

        unsigned a[4][4];
        #pragma unroll
        for (int ks = 0; ks < 4; ks++) {
            int k0 = ks * 8;
            a[ks][0] = sEt[(m0 + g) * 36 + k0 + tid4];
            a[ks][1] = sEt[(m0 + g + 8) * 36 + k0 + tid4];
            a[ks][2] = sEt[(m0 + g) * 36 + k0 + tid4 + 4];
            a[ks][3] = sEt[(m0 + g + 8) * 36 + k0 + tid4 + 4];
        }
        const float* row0 = g_h1 + (size_t)sSrc[m0 + g] * 128;
        const float* row1 = g_h1 + (size_t)sSrc[m0 + g + 8] * 128;

        #pragma unroll
        for (int nt = 0; nt < 8; nt++) {
            int ntg = ntb + nt;
            int jb = ntg * 8 + 2 * tid4;
            float2 ha = *(const float2*)&row0[jb];
            float2 hb = *(const float2*)&row1[jb];
            float c0 = ha.x, c1 = ha.y, c2 = hb.x, c3 = hb.y;
            #pragma unroll
            for (int ks = 0; ks < 4; ks++) {
                uint2 bb = g_WcF[(ntg * 4 + ks) * 32 + lane];
                mma_tf32(c0, c1, c2, c3, a[ks][0], a[ks][1], a[ks][2], a[ks][3], bb.x, bb.y);
            }
            *(float2*)&sM[(m0 + g) * 132 + jb]     = make_float2(c0, c1);
            *(float2*)&sM[(m0 + g + 8) * 132 + jb] = make_float2(c2, c3);
        }
    }
    __syncthreads();

    // epilogue: 2 threads per column; thread (j = t&127, half = t>>7) scans 32 rows.
    // Boundary runs merge via two atomicMax into the same slot (max commutative).
    // sM already contains h1[src] + eh; cur=0 absorbs relu; int-max exact for >=0.
    {
        int j = t & 127;
        int r0 = (t >> 7) * 32;
        float cur = 0.f;
        int dprev = sDst[r0];
        #pragma unroll 8
        for (int r = r0; r < r0 + 32; r++) {
            int d = sDst[r];
            float v = sM[r * 132 + j];
            if (d != dprev) {
                atomicMax(&g_neigh[(size_t)dprev * 128 + j], __float_as_int(cur));
                cur = 0.f;
                dprev = d;
            }
            cur = fmaxf(cur, v);
        }
        atomicMax(&g_neigh[(size_t)dprev * 128 + j], __float_as_int(cur));
    }
}

// ---------------- final: out = self + (1+eps)*neigh ----------------
__global__ void k_final(const float* __restrict__ eps, float* __restrict__ out) {
    float s = 1.0f + eps[0];
    int idx = blockIdx.x * blockDim.x + threadIdx.x;  // NN*128/4
    float4 o = ((float4*)out)[idx];
    int4 nb = ((const int4*)g_neigh)[idx];
    o.x = fmaf(s, __int_as_float(nb.x), o.x);
    o.y = fmaf(s, __int_as_float(nb.y), o.y);
    o.z = fmaf(s, __int_as_float(nb.z), o.z);
    o.w = fmaf(s, __int_as_float(nb.w), o.w);
    ((float4*)out)[idx] = o;
}

extern "C" void kernel_launch(void* const* d_in, const int* in_sizes, int n_in,
                              void* d_out, int out_size) {
    const float* nfeat  = (const float*)d_in[0];
    const float* etype  = (const float*)d_in[1];
    const int*   src    = (const int*)d_in[2];
    const int*   dst    = (const int*)d_in[3];
    const float* W_edge = (const float*)d_in[4];
    const float* W_ne   = (const float*)d_in[5];
    const float* b_ne   = (const float*)d_in[6];
    const float* W_self = (const float*)d_in[7];
    const float* b_self = (const float*)d_in[8];
    const float* eps    = (const float*)d_in[9];
    float* out = (float*)d_out;

    // Fork/join with two extra streams; all created AND destroyed per call so
    // the harness memory checkpoints see zero delta (destroy after rejoin).
    cudaStream_t s1, s2;
    cudaStreamCreateWithFlags(&s1, cudaStreamNonBlocking);
    cudaStreamCreateWithFlags(&s2, cudaStreamNonBlocking);
    cudaEvent_t e0, e1, e2;
    cudaEventCreateWithFlags(&e0, cudaEventDisableTiming);
    cudaEventCreateWithFlags(&e1, cudaEventDisableTiming);
    cudaEventCreateWithFlags(&e2, cudaEventDisableTiming);

    cudaEventRecord(e0, 0);          // fork point on the main stream

    // s1: weights + node GEMM chain
    cudaStreamWaitEvent(s1, e0, 0);
    k_wc<<<32, 128, 0, s1>>>(W_ne, W_edge);
    k_wpack<<<8, 256, 0, s1>>>();
    k_prep<<<64, 256, 0, s1>>>(W_ne, W_self);
    k_node<<<(NN + 31) / 32, 128, 0, s1>>>(nfeat, b_ne, b_self, out);
    cudaEventRecord(e1, s1);

    // s2: neigh zero (only needed by k_edge)
    cudaStreamWaitEvent(s2, e0, 0);
    k_zero_neigh<<<6250, 256, 0, s2>>>();
    cudaEventRecord(e2, s2);

    // main stream: CSR build chain
    k_zero_deg<<<(NN + 255) / 256, 256>>>();
    k_count<<<(EE + 255) / 256, 256>>>(dst);
    k_scanA<<<SCAN_BLOCKS, 1024>>>();
    k_scanB<<<1, 64>>>();
    k_scanC<<<SCAN_BLOCKS, 1024>>>();
    k_scatter<<<(EE + 255) / 256, 256>>>(dst, src);

    // join: k_edge needs g_WcF + g_h1 (s1), zeroed neigh (s2), CSR (main)
    cudaStreamWaitEvent(0, e1, 0);
    cudaStreamWaitEvent(0, e2, 0);
    k_edge<<<EE / 64, 256>>>(etype);
    k_final<<<(NN * 128 / 4) / 256, 256>>>(eps, out);

    cudaEventDestroy(e0);
    cudaEventDestroy(e1);
    cudaEventDestroy(e2);
    cudaStreamDestroy(s1);
    cudaStreamDestroy(s2);
}